// round 10
// baseline (speedup 1.0000x reference)
#include <cuda_runtime.h>
#include <cuda_bf16.h>
#include <cuda_fp16.h>
#include <cstdint>

#define NN 100000
#define EE 1600000
#define DD 128
#define SCAN_BLK 1024
#define GPITCH 136   // bf16 elements per smem row (128 + 8 pad -> conflict-free ldmatrix)

// ---------------- scratch (static device arrays; no allocation) ----------------
__device__ __half g_h[(size_t)NN * DD];   // gemm1 out / agg2 out
__device__ __half g_z[(size_t)NN * DD];   // fused(agg1+gemm2) out
__device__ int   g_count[NN];
__device__ int   g_rowptr[NN + 1];
__device__ int   g_cursor[NN];
__device__ float g_dinv[NN];
__device__ int   g_csrc[EE];
__device__ float g_cw[EE];
__device__ int   g_blocksum[1024];
// bf16 split of W1^T / W2^T : [n][k] layout
__device__ __nv_bfloat16 g_w1hi[DD * DD];
__device__ __nv_bfloat16 g_w1lo[DD * DD];
__device__ __nv_bfloat16 g_w2hi[DD * DD];
__device__ __nv_bfloat16 g_w2lo[DD * DD];

__device__ __forceinline__ uint32_t smem_u32(const void* p) {
    uint32_t a;
    asm("{ .reg .u64 t; cvta.to.shared.u64 t, %1; cvt.u32.u64 %0, t; }" : "=r"(a) : "l"(p));
    return a;
}

// ---------------- preprocessing ----------------
__global__ void zero_count_kernel(int n) {
    int i = blockIdx.x * blockDim.x + threadIdx.x;
    if (i < n) g_count[i] = 0;
}

__global__ void convert_w_kernel(const float* __restrict__ W1, const float* __restrict__ W2) {
    int i = blockIdx.x * blockDim.x + threadIdx.x;
    if (i >= DD * DD) return;
    int nn = i >> 7, kk = i & 127;
    float w1 = W1[kk * DD + nn];
    __nv_bfloat16 h1 = __float2bfloat16(w1);
    g_w1hi[nn * DD + kk] = h1;
    g_w1lo[nn * DD + kk] = __float2bfloat16(w1 - __bfloat162float(h1));
    float w2 = W2[kk * DD + nn];
    __nv_bfloat16 h2 = __float2bfloat16(w2);
    g_w2hi[nn * DD + kk] = h2;
    g_w2lo[nn * DD + kk] = __float2bfloat16(w2 - __bfloat162float(h2));
}

__global__ void count_kernel(const int* __restrict__ ei, int E, int n) {
    int t = blockIdx.x * blockDim.x + threadIdx.x;
    int e = t * 4;
    if (e + 3 < E) {
        int4 d4 = *(const int4*)(ei + (size_t)E + e);
        if ((unsigned)d4.x < (unsigned)n) atomicAdd(&g_count[d4.x], 1);
        if ((unsigned)d4.y < (unsigned)n) atomicAdd(&g_count[d4.y], 1);
        if ((unsigned)d4.z < (unsigned)n) atomicAdd(&g_count[d4.z], 1);
        if ((unsigned)d4.w < (unsigned)n) atomicAdd(&g_count[d4.w], 1);
    } else {
        for (; e < E; e++) {
            int d = ei[(size_t)E + e];
            if ((unsigned)d < (unsigned)n) atomicAdd(&g_count[d], 1);
        }
    }
}

__device__ __forceinline__ int block_scan_incl(int v, int* wsum) {
    int lane = threadIdx.x & 31, wid = threadIdx.x >> 5;
    int x = v;
    #pragma unroll
    for (int off = 1; off < 32; off <<= 1) {
        int y = __shfl_up_sync(0xFFFFFFFFu, x, off);
        if (lane >= off) x += y;
    }
    if (lane == 31) wsum[wid] = x;
    __syncthreads();
    if (wid == 0) {
        int s = wsum[lane];
        #pragma unroll
        for (int off = 1; off < 32; off <<= 1) {
            int y = __shfl_up_sync(0xFFFFFFFFu, s, off);
            if (lane >= off) s += y;
        }
        wsum[lane] = s;
    }
    __syncthreads();
    return x + (wid > 0 ? wsum[wid - 1] : 0);
}

__global__ __launch_bounds__(SCAN_BLK) void scan1_kernel(int n) {
    __shared__ int wsum[32];
    int idx = blockIdx.x * SCAN_BLK + threadIdx.x;
    int v = (idx < n) ? g_count[idx] : 0;
    if (idx < n) g_dinv[idx] = rsqrtf((float)v + 1.0f);   // +1 self loop
    int incl = block_scan_incl(v, wsum);
    if (idx < n) g_rowptr[idx] = incl - v;
    if (threadIdx.x == SCAN_BLK - 1) g_blocksum[blockIdx.x] = incl;
}

__global__ __launch_bounds__(SCAN_BLK) void scan3_kernel(int n, int nb) {
    __shared__ int s_off;
    int bid = blockIdx.x;
    if (threadIdx.x < 32) {
        int s = 0;
        for (int j = threadIdx.x; j < bid; j += 32) s += g_blocksum[j];
        #pragma unroll
        for (int o = 16; o; o >>= 1) s += __shfl_down_sync(0xFFFFFFFFu, s, o);
        if (threadIdx.x == 0) s_off = s;
    }
    __syncthreads();
    int idx = bid * SCAN_BLK + threadIdx.x;
    if (idx < n) {
        int r = g_rowptr[idx] + s_off;
        g_rowptr[idx] = r;
        g_cursor[idx] = r;
    }
    if (bid == nb - 1 && threadIdx.x == 0)
        g_rowptr[n] = s_off + g_blocksum[nb - 1];
}

__global__ void fill_kernel(const int* __restrict__ ei, int E, int n) {
    int t = blockIdx.x * blockDim.x + threadIdx.x;
    int e = t * 4;
    if (e + 3 < E) {
        int4 s4 = *(const int4*)(ei + e);
        int4 d4 = *(const int4*)(ei + (size_t)E + e);
        #pragma unroll
        for (int j = 0; j < 4; j++) {
            int s = (&s4.x)[j], d = (&d4.x)[j];
            if ((unsigned)s < (unsigned)n && (unsigned)d < (unsigned)n) {
                int p = atomicAdd(&g_cursor[d], 1);
                g_csrc[p] = s;
                g_cw[p] = g_dinv[s] * g_dinv[d];
            }
        }
    } else {
        for (; e < E; e++) {
            int s = ei[e], d = ei[(size_t)E + e];
            if ((unsigned)s < (unsigned)n && (unsigned)d < (unsigned)n) {
                int p = atomicAdd(&g_cursor[d], 1);
                g_csrc[p] = s;
                g_cw[p] = g_dinv[s] * g_dinv[d];
            }
        }
    }
}

// ---------------- mma.sync helpers ----------------
__device__ __forceinline__ void ldsm_x4(uint32_t addr, uint32_t& r0, uint32_t& r1, uint32_t& r2, uint32_t& r3) {
    asm volatile("ldmatrix.sync.aligned.m8n8.x4.shared.b16 {%0,%1,%2,%3}, [%4];"
        : "=r"(r0), "=r"(r1), "=r"(r2), "=r"(r3) : "r"(addr));
}
__device__ __forceinline__ void mma_bf16(float* c, uint32_t a0, uint32_t a1, uint32_t a2, uint32_t a3,
                                         uint32_t b0, uint32_t b1) {
    asm volatile("mma.sync.aligned.m16n8k16.row.col.f32.bf16.bf16.f32 "
        "{%0,%1,%2,%3}, {%4,%5,%6,%7}, {%8,%9}, {%0,%1,%2,%3};"
        : "+f"(c[0]), "+f"(c[1]), "+f"(c[2]), "+f"(c[3])
        : "r"(a0), "r"(a1), "r"(a2), "r"(a3), "r"(b0), "r"(b1));
}

__device__ __forceinline__ float4 load4(const float* p) { return *(const float4*)p; }
__device__ __forceinline__ float4 half4_to_float4(uint2 raw) {
    __half2 p0 = *reinterpret_cast<__half2*>(&raw.x);
    __half2 p1 = *reinterpret_cast<__half2*>(&raw.y);
    float2 f0 = __half22float2(p0), f1 = __half22float2(p1);
    return make_float4(f0.x, f0.y, f1.x, f1.y);
}
__device__ __forceinline__ float4 load4(const __half* p) { return half4_to_float4(*(const uint2*)p); }

#define GSM_BYTES (4 * 128 * GPITCH * 2)

// shared MMA phase: X/W tiles in smem -> C fp16
__device__ __forceinline__ void mma_phase(uint32_t sbase, __half* __restrict__ C,
                                          int block_row, int n, int w, int l) {
    uint32_t a_off = (uint32_t)(((w * 16 + (l & 15)) * GPITCH + (l >> 4) * 8) * 2);
    uint32_t ahi_addr = sbase + a_off;
    uint32_t alo_addr = sbase + (uint32_t)(128 * GPITCH * 2) + a_off;
    uint32_t b_off = (uint32_t)((((l & 7) + ((l >> 4) << 3)) * GPITCH + ((l >> 3) & 1) * 8) * 2);
    uint32_t bhi_addr = sbase + (uint32_t)(2 * 128 * GPITCH * 2) + b_off;
    uint32_t blo_addr = sbase + (uint32_t)(3 * 128 * GPITCH * 2) + b_off;

    float acc[16][4];
    #pragma unroll
    for (int j = 0; j < 16; j++)
        #pragma unroll
        for (int q = 0; q < 4; q++) acc[j][q] = 0.0f;

    #pragma unroll
    for (int kk = 0; kk < 8; kk++) {
        uint32_t ka = kk * 32;
        uint32_t ah0, ah1, ah2, ah3, al0, al1, al2, al3;
        ldsm_x4(ahi_addr + ka, ah0, ah1, ah2, ah3);
        ldsm_x4(alo_addr + ka, al0, al1, al2, al3);
        #pragma unroll
        for (int j2 = 0; j2 < 8; j2++) {
            uint32_t boff = (uint32_t)(j2 * 16 * GPITCH * 2) + ka;
            uint32_t bh0, bh1, bh2, bh3, bl0, bl1, bl2, bl3;
            ldsm_x4(bhi_addr + boff, bh0, bh1, bh2, bh3);
            ldsm_x4(blo_addr + boff, bl0, bl1, bl2, bl3);
            mma_bf16(acc[2 * j2],     ah0, ah1, ah2, ah3, bh0, bh1);
            mma_bf16(acc[2 * j2],     al0, al1, al2, al3, bh0, bh1);
            mma_bf16(acc[2 * j2],     ah0, ah1, ah2, ah3, bl0, bl1);
            mma_bf16(acc[2 * j2 + 1], ah0, ah1, ah2, ah3, bh2, bh3);
            mma_bf16(acc[2 * j2 + 1], al0, al1, al2, al3, bh2, bh3);
            mma_bf16(acc[2 * j2 + 1], ah0, ah1, ah2, ah3, bl2, bl3);
        }
    }

    int g = l >> 2, t = l & 3;
    int row0 = block_row + w * 16 + g;
    int row1 = row0 + 8;
    #pragma unroll
    for (int j = 0; j < 16; j++) {
        int col = j * 8 + t * 2;
        if (row0 < n) *(__half2*)(C + (size_t)row0 * 128 + col) = __floats2half2_rn(acc[j][0], acc[j][1]);
        if (row1 < n) *(__half2*)(C + (size_t)row1 * 128 + col) = __floats2half2_rn(acc[j][2], acc[j][3]);
    }
}

__device__ __forceinline__ void store_split(__nv_bfloat16* Xhi, __nv_bfloat16* Xlo,
                                            int r, int c, float4 v) {
    __nv_bfloat16 h0 = __float2bfloat16(v.x), h1 = __float2bfloat16(v.y);
    __nv_bfloat16 h2 = __float2bfloat16(v.z), h3 = __float2bfloat16(v.w);
    *(__nv_bfloat162*)&Xhi[r * GPITCH + c]     = __nv_bfloat162(h0, h1);
    *(__nv_bfloat162*)&Xhi[r * GPITCH + c + 2] = __nv_bfloat162(h2, h3);
    *(__nv_bfloat162*)&Xlo[r * GPITCH + c] =
        __nv_bfloat162(__float2bfloat16(v.x - __bfloat162float(h0)),
                       __float2bfloat16(v.y - __bfloat162float(h1)));
    *(__nv_bfloat162*)&Xlo[r * GPITCH + c + 2] =
        __nv_bfloat162(__float2bfloat16(v.z - __bfloat162float(h2)),
                       __float2bfloat16(v.w - __bfloat162float(h3)));
}

// ---------------- GEMM (layer 1): fp32 X in global -> fp16 out ----------------
__global__ __launch_bounds__(256) void gemm_mma_kernel(
    const float* __restrict__ A,
    const __nv_bfloat16* __restrict__ Wthi,
    const __nv_bfloat16* __restrict__ Wtlo,
    __half* __restrict__ C, int n)
{
    extern __shared__ __align__(16) __nv_bfloat16 sm[];
    __nv_bfloat16* Xhi = sm;
    __nv_bfloat16* Xlo = Xhi + 128 * GPITCH;
    __nv_bfloat16* Whi = Xlo + 128 * GPITCH;
    __nv_bfloat16* Wlo = Whi + 128 * GPITCH;

    int tid = threadIdx.x;
    int w = tid >> 5, l = tid & 31;
    int block_row = blockIdx.x * 128;

    #pragma unroll
    for (int it = 0; it < 16; it++) {
        int idx = tid + it * 256;
        int r = idx >> 5;
        int c = (idx & 31) * 4;
        int grow = block_row + r;
        float4 v = make_float4(0.f, 0.f, 0.f, 0.f);
        if (grow < n) v = load4(A + (size_t)grow * 128 + c);
        store_split(Xhi, Xlo, r, c, v);
    }
    #pragma unroll
    for (int it = 0; it < 32; it++) {
        int idx = tid + it * 256;
        int r = idx >> 6;
        int c = (idx & 63) * 2;
        *(uint32_t*)&Whi[r * GPITCH + c] = *(const uint32_t*)(Wthi + (size_t)r * 128 + c);
        *(uint32_t*)&Wlo[r * GPITCH + c] = *(const uint32_t*)(Wtlo + (size_t)r * 128 + c);
    }
    __syncthreads();
    mma_phase(smem_u32(sm), C, block_row, n, w, l);
}

// ---------------- fused agg(layer1) + GEMM(layer2): h fp16 -> z1 in smem -> h2 fp16 ------
__global__ __launch_bounds__(256) void agg_gemm_kernel(
    const __half* __restrict__ h, const float* __restrict__ bias,
    const __nv_bfloat16* __restrict__ Wthi,
    const __nv_bfloat16* __restrict__ Wtlo,
    __half* __restrict__ C, int n)
{
    extern __shared__ __align__(16) __nv_bfloat16 sm[];
    __nv_bfloat16* Xhi = sm;
    __nv_bfloat16* Xlo = Xhi + 128 * GPITCH;
    __nv_bfloat16* Whi = Xlo + 128 * GPITCH;
    __nv_bfloat16* Wlo = Whi + 128 * GPITCH;

    int tid = threadIdx.x;
    int w = tid >> 5, l = tid & 31;
    int block_row = blockIdx.x * 128;

    // W tiles
    #pragma unroll
    for (int it = 0; it < 32; it++) {
        int idx = tid + it * 256;
        int r = idx >> 6;
        int c = (idx & 63) * 2;
        *(uint32_t*)&Whi[r * GPITCH + c] = *(const uint32_t*)(Wthi + (size_t)r * 128 + c);
        *(uint32_t*)&Wlo[r * GPITCH + c] = *(const uint32_t*)(Wtlo + (size_t)r * 128 + c);
    }

    float4 bb = ((const float4*)bias)[l];
    int c = l * 4;

    // aggregation phase: warp w handles rows {w, w+8, ..., w+120}
    for (int rr = 0; rr < 16; rr++) {
        int r = rr * 8 + w;
        int i = block_row + r;
        float4 acc = make_float4(0.f, 0.f, 0.f, 0.f);
        if (i < n) {
            float di = g_dinv[i];
            float w0 = di * di;
            float4 v = half4_to_float4(((const uint2*)(h + (size_t)i * 128))[l]);
            acc = make_float4(v.x * w0, v.y * w0, v.z * w0, v.w * w0);
            float4 acc2 = make_float4(0.f, 0.f, 0.f, 0.f);
            int e0 = g_rowptr[i], e1 = g_rowptr[i + 1];
            int e = e0;
            for (; e + 7 < e1; e += 8) {
                uint2 rr0 = ((const uint2*)(h + (size_t)g_csrc[e]     * 128))[l];
                uint2 rr1 = ((const uint2*)(h + (size_t)g_csrc[e + 1] * 128))[l];
                uint2 rr2 = ((const uint2*)(h + (size_t)g_csrc[e + 2] * 128))[l];
                uint2 rr3 = ((const uint2*)(h + (size_t)g_csrc[e + 3] * 128))[l];
                uint2 rr4 = ((const uint2*)(h + (size_t)g_csrc[e + 4] * 128))[l];
                uint2 rr5 = ((const uint2*)(h + (size_t)g_csrc[e + 5] * 128))[l];
                uint2 rr6 = ((const uint2*)(h + (size_t)g_csrc[e + 6] * 128))[l];
                uint2 rr7 = ((const uint2*)(h + (size_t)g_csrc[e + 7] * 128))[l];
                float w_0 = g_cw[e],     w_1 = g_cw[e + 1], w_2 = g_cw[e + 2], w_3 = g_cw[e + 3];
                float w_4 = g_cw[e + 4], w_5 = g_cw[e + 5], w_6 = g_cw[e + 6], w_7 = g_cw[e + 7];
                float4 h0 = half4_to_float4(rr0), h1 = half4_to_float4(rr1);
                float4 h2 = half4_to_float4(rr2), h3 = half4_to_float4(rr3);
                float4 h4 = half4_to_float4(rr4), h5 = half4_to_float4(rr5);
                float4 h6 = half4_to_float4(rr6), h7 = half4_to_float4(rr7);
                acc.x  = fmaf(h0.x, w_0, acc.x);  acc.y  = fmaf(h0.y, w_0, acc.y);
                acc.z  = fmaf(h0.z, w_0, acc.z);  acc.w  = fmaf(h0.w, w_0, acc.w);
                acc2.x = fmaf(h1.x, w_1, acc2.x); acc2.y = fmaf(h1.y, w_1, acc2.y);
                acc2.z = fmaf(h1.z, w_1, acc2.z); acc2.w = fmaf(h1.w, w_1, acc2.w);
                acc.x  = fmaf(h2.x, w_2, acc.x);  acc.y  = fmaf(h2.y, w_2, acc.y);
                acc.z  = fmaf(h2.z, w_2, acc.z);  acc.w  = fmaf(h2.w, w_2, acc.w);
                acc2.x = fmaf(h3.x, w_3, acc2.x); acc2.y = fmaf(h3.y, w_3, acc2.y);
                acc2.z = fmaf(h3.z, w_3, acc2.z); acc2.w = fmaf(h3.w, w_3, acc2.w);
                acc.x  = fmaf(h4.x, w_4, acc.x);  acc.y  = fmaf(h4.y, w_4, acc.y);
                acc.z  = fmaf(h4.z, w_4, acc.z);  acc.w  = fmaf(h4.w, w_4, acc.w);
                acc2.x = fmaf(h5.x, w_5, acc2.x); acc2.y = fmaf(h5.y, w_5, acc2.y);
                acc2.z = fmaf(h5.z, w_5, acc2.z); acc2.w = fmaf(h5.w, w_5, acc2.w);
                acc.x  = fmaf(h6.x, w_6, acc.x);  acc.y  = fmaf(h6.y, w_6, acc.y);
                acc.z  = fmaf(h6.z, w_6, acc.z);  acc.w  = fmaf(h6.w, w_6, acc.w);
                acc2.x = fmaf(h7.x, w_7, acc2.x); acc2.y = fmaf(h7.y, w_7, acc2.y);
                acc2.z = fmaf(h7.z, w_7, acc2.z); acc2.w = fmaf(h7.w, w_7, acc2.w);
            }
            for (; e < e1; e++) {
                float w_0 = g_cw[e];
                float4 h0 = half4_to_float4(((const uint2*)(h + (size_t)g_csrc[e] * 128))[l]);
                acc.x = fmaf(h0.x, w_0, acc.x); acc.y = fmaf(h0.y, w_0, acc.y);
                acc.z = fmaf(h0.z, w_0, acc.z); acc.w = fmaf(h0.w, w_0, acc.w);
            }
            acc.x += acc2.x; acc.y += acc2.y; acc.z += acc2.z; acc.w += acc2.w;
            acc.x = fmaxf(acc.x + bb.x, 0.0f);
            acc.y = fmaxf(acc.y + bb.y, 0.0f);
            acc.z = fmaxf(acc.z + bb.z, 0.0f);
            acc.w = fmaxf(acc.w + bb.w, 0.0f);
        }
        store_split(Xhi, Xlo, r, c, acc);
    }
    __syncthreads();
    mma_phase(smem_u32(sm), C, block_row, n, w, l);
}

// ---------------- aggregation (layer 2, standalone) ----------------
__global__ __launch_bounds__(256) void aggregate_kernel(
    const __half* __restrict__ h, const float* __restrict__ bias,
    __half* __restrict__ out, int n)
{
    int warp = (blockIdx.x * blockDim.x + threadIdx.x) >> 5;
    int lane = threadIdx.x & 31;
    if (warp >= n) return;
    int i = warp;

    float di = g_dinv[i];
    float w0 = di * di;
    float4 v = half4_to_float4(((const uint2*)(h + (size_t)i * 128))[lane]);
    float4 acc  = make_float4(v.x * w0, v.y * w0, v.z * w0, v.w * w0);
    float4 acc2 = make_float4(0.f, 0.f, 0.f, 0.f);

    int e0 = g_rowptr[i], e1 = g_rowptr[i + 1];
    int e = e0;
    for (; e + 3 < e1; e += 4) {
        int s0 = g_csrc[e];     float w_0 = g_cw[e];
        int s1 = g_csrc[e + 1]; float w_1 = g_cw[e + 1];
        int s2 = g_csrc[e + 2]; float w_2 = g_cw[e + 2];
        int s3 = g_csrc[e + 3]; float w_3 = g_cw[e + 3];
        uint2 r0 = ((const uint2*)(h + (size_t)s0 * 128))[lane];
        uint2 r1 = ((const uint2*)(h + (size_t)s1 * 128))[lane];
        uint2 r2 = ((const uint2*)(h + (size_t)s2 * 128))[lane];
        uint2 r3 = ((const uint2*)(h + (size_t)s3 * 128))[lane];
        float4 h0 = half4_to_float4(r0), h1 = half4_to_float4(r1);
        float4 h2 = half4_to_float4(r2), h3 = half4_to_float4(r3);
        acc.x  = fmaf(h0.x, w_0, acc.x);  acc.y  = fmaf(h0.y, w_0, acc.y);
        acc.z  = fmaf(h0.z, w_0, acc.z);  acc.w  = fmaf(h0.w, w_0, acc.w);
        acc2.x = fmaf(h1.x, w_1, acc2.x); acc2.y = fmaf(h1.y, w_1, acc2.y);
        acc2.z = fmaf(h1.z, w_1, acc2.z); acc2.w = fmaf(h1.w, w_1, acc2.w);
        acc.x  = fmaf(h2.x, w_2, acc.x);  acc.y  = fmaf(h2.y, w_2, acc.y);
        acc.z  = fmaf(h2.z, w_2, acc.z);  acc.w  = fmaf(h2.w, w_2, acc.w);
        acc2.x = fmaf(h3.x, w_3, acc2.x); acc2.y = fmaf(h3.y, w_3, acc2.y);
        acc2.z = fmaf(h3.z, w_3, acc2.z); acc2.w = fmaf(h3.w, w_3, acc2.w);
    }
    for (; e < e1; e++) {
        int s0 = g_csrc[e]; float w_0 = g_cw[e];
        float4 h0 = half4_to_float4(((const uint2*)(h + (size_t)s0 * 128))[lane]);
        acc.x = fmaf(h0.x, w_0, acc.x); acc.y = fmaf(h0.y, w_0, acc.y);
        acc.z = fmaf(h0.z, w_0, acc.z); acc.w = fmaf(h0.w, w_0, acc.w);
    }
    acc.x += acc2.x; acc.y += acc2.y; acc.z += acc2.z; acc.w += acc2.w;

    float4 bb = ((const float4*)bias)[lane];
    acc.x = fmaxf(acc.x + bb.x, 0.0f);
    acc.y = fmaxf(acc.y + bb.y, 0.0f);
    acc.z = fmaxf(acc.z + bb.z, 0.0f);
    acc.w = fmaxf(acc.w + bb.w, 0.0f);
    uint2 packed;
    *reinterpret_cast<__half2*>(&packed.x) = __floats2half2_rn(acc.x, acc.y);
    *reinterpret_cast<__half2*>(&packed.y) = __floats2half2_rn(acc.z, acc.w);
    ((uint2*)(out + (size_t)i * 128))[lane] = packed;
}

// ---------------- decode ----------------
__global__ __launch_bounds__(256) void decode_kernel(
    const __half* __restrict__ z, const int* __restrict__ eli,
    float* __restrict__ out, int el)
{
    int warp = (blockIdx.x * blockDim.x + threadIdx.x) >> 5;
    int lane = threadIdx.x & 31;
    if (warp >= el) return;
    int s = eli[warp];
    int d = eli[(size_t)el + warp];
    float4 a = half4_to_float4(((const uint2*)(z + (size_t)s * 128))[lane]);
    float4 b = half4_to_float4(((const uint2*)(z + (size_t)d * 128))[lane]);
    float p = a.x * b.x + a.y * b.y + a.z * b.z + a.w * b.w;
    #pragma unroll
    for (int off = 16; off; off >>= 1) p += __shfl_down_sync(0xFFFFFFFFu, p, off);
    if (lane == 0) out[warp] = p;
}

// ---------------- launch ----------------
extern "C" void kernel_launch(void* const* d_in, const int* in_sizes, int n_in,
                              void* d_out, int out_size)
{
    const float* x   = (const float*)d_in[0];
    const int*   ei  = (const int*)d_in[1];    // int64 tensors arrive as int32
    const int*   eli = (const int*)d_in[2];
    const float* W1  = (const float*)d_in[3];
    const float* b1  = (const float*)d_in[4];
    const float* W2  = (const float*)d_in[5];
    const float* b2  = (const float*)d_in[6];
    float* out = (float*)d_out;

    int n  = in_sizes[0] / DD;
    int E  = in_sizes[1] / 2;
    int el = in_sizes[2] / 2;

    __half* h = nullptr; __half* z = nullptr;
    __nv_bfloat16 *w1hi = nullptr, *w1lo = nullptr, *w2hi = nullptr, *w2lo = nullptr;
    cudaGetSymbolAddress((void**)&h, g_h);
    cudaGetSymbolAddress((void**)&z, g_z);
    cudaGetSymbolAddress((void**)&w1hi, g_w1hi);
    cudaGetSymbolAddress((void**)&w1lo, g_w1lo);
    cudaGetSymbolAddress((void**)&w2hi, g_w2hi);
    cudaGetSymbolAddress((void**)&w2lo, g_w2lo);

    cudaFuncSetAttribute(gemm_mma_kernel, cudaFuncAttributeMaxDynamicSharedMemorySize, GSM_BYTES);
    cudaFuncSetAttribute(agg_gemm_kernel, cudaFuncAttributeMaxDynamicSharedMemorySize, GSM_BYTES);

    const int T = 256;
    int nb_n = (n + T - 1) / T;
    int nE4 = (E + 3) / 4;
    int nb_e4 = (nE4 + T - 1) / T;
    int nb_warpN = (n * 32 + T - 1) / T;
    int nb_warpL = (el * 32 + T - 1) / T;
    int nb_gemm = (n + 127) / 128;
    int nb_scan = (n + SCAN_BLK - 1) / SCAN_BLK;

    // fork a side stream: convert_w + gemm1 run concurrently with the prep chain
    cudaStream_t s2;
    cudaEvent_t evFork, evJoin;
    cudaStreamCreateWithFlags(&s2, cudaStreamNonBlocking);
    cudaEventCreateWithFlags(&evFork, cudaEventDisableTiming);
    cudaEventCreateWithFlags(&evJoin, cudaEventDisableTiming);

    cudaEventRecord(evFork, 0);
    cudaStreamWaitEvent(s2, evFork, 0);

    // side stream: weight split + layer-1 GEMM
    convert_w_kernel<<<(DD * DD + T - 1) / T, T, 0, s2>>>(W1, W2);
    gemm_mma_kernel<<<nb_gemm, T, GSM_BYTES, s2>>>(x, w1hi, w1lo, h, n);
    cudaEventRecord(evJoin, s2);

    // default stream: graph preprocessing
    zero_count_kernel<<<nb_n, T>>>(n);
    count_kernel<<<nb_e4, T>>>(ei, E, n);
    scan1_kernel<<<nb_scan, SCAN_BLK>>>(n);
    scan3_kernel<<<nb_scan, SCAN_BLK>>>(n, nb_scan);
    fill_kernel<<<nb_e4, T>>>(ei, E, n);

    // join, then fused agg1+gemm2: reads g_h, writes g_z
    cudaStreamWaitEvent(0, evJoin, 0);
    agg_gemm_kernel<<<nb_gemm, T, GSM_BYTES>>>(h, b1, w2hi, w2lo, z, n);

    // layer-2 aggregation: reads g_z, writes g_h
    aggregate_kernel<<<nb_warpN, T>>>(z, b2, h, n);

    // decode from g_h
    decode_kernel<<<nb_warpL, T>>>(h, eli, out, el);
}

// round 11
// speedup vs baseline: 1.4817x; 1.4817x over previous
#include <cuda_runtime.h>
#include <cuda_bf16.h>
#include <cuda_fp16.h>
#include <cstdint>

#define NN 100000
#define EE 1600000
#define DD 128
#define SCAN_BLK 1024
#define GPITCH 136   // bf16 elements per smem row (128 + 8 pad -> conflict-free ldmatrix)

// ---------------- scratch (static device arrays; no allocation) ----------------
__device__ __half g_h[(size_t)NN * DD];   // GEMM output (fp16), aggregation input
__device__ __half g_z[(size_t)NN * DD];   // aggregation output (fp16)
__device__ int   g_count[NN];
__device__ int   g_rowptr[NN + 1];
__device__ int   g_cursor[NN];
__device__ float g_dinv[NN];
__device__ int   g_csrc[EE];
__device__ int   g_blocksum[1024];
__device__ int   g_blockoff[1025];
// bf16 split of W1^T / W2^T : [n][k] layout (row = output col, k contiguous)
__device__ __nv_bfloat16 g_w1hi[DD * DD];
__device__ __nv_bfloat16 g_w1lo[DD * DD];
__device__ __nv_bfloat16 g_w2hi[DD * DD];
__device__ __nv_bfloat16 g_w2lo[DD * DD];

__device__ __forceinline__ uint32_t smem_u32(const void* p) {
    uint32_t a;
    asm("{ .reg .u64 t; cvta.to.shared.u64 t, %1; cvt.u32.u64 %0, t; }" : "=r"(a) : "l"(p));
    return a;
}

// ---------------- preprocessing kernels ----------------
__global__ void zero_count_kernel(int n) {
    int i = blockIdx.x * blockDim.x + threadIdx.x;
    if (i < n) g_count[i] = 0;
}

// split W1/W2 to bf16 hi/lo (side stream)
__global__ void convert_w_kernel(const float* __restrict__ W1, const float* __restrict__ W2) {
    int i = blockIdx.x * blockDim.x + threadIdx.x;
    if (i >= DD * DD) return;
    int nn = i >> 7, kk = i & 127;
    float w1 = W1[kk * DD + nn];
    __nv_bfloat16 h1 = __float2bfloat16(w1);
    g_w1hi[nn * DD + kk] = h1;
    g_w1lo[nn * DD + kk] = __float2bfloat16(w1 - __bfloat162float(h1));
    float w2 = W2[kk * DD + nn];
    __nv_bfloat16 h2 = __float2bfloat16(w2);
    g_w2hi[nn * DD + kk] = h2;
    g_w2lo[nn * DD + kk] = __float2bfloat16(w2 - __bfloat162float(h2));
}

// 4 edges per thread (int4 load of dst)
__global__ void count_kernel(const int* __restrict__ ei, int E, int n) {
    int t = blockIdx.x * blockDim.x + threadIdx.x;
    int e = t * 4;
    if (e + 3 < E) {
        int4 d4 = *(const int4*)(ei + (size_t)E + e);
        if ((unsigned)d4.x < (unsigned)n) atomicAdd(&g_count[d4.x], 1);
        if ((unsigned)d4.y < (unsigned)n) atomicAdd(&g_count[d4.y], 1);
        if ((unsigned)d4.z < (unsigned)n) atomicAdd(&g_count[d4.z], 1);
        if ((unsigned)d4.w < (unsigned)n) atomicAdd(&g_count[d4.w], 1);
    } else {
        for (; e < E; e++) {
            int d = ei[(size_t)E + e];
            if ((unsigned)d < (unsigned)n) atomicAdd(&g_count[d], 1);
        }
    }
}

__device__ __forceinline__ int block_scan_incl(int v, int* wsum) {
    int lane = threadIdx.x & 31, wid = threadIdx.x >> 5;
    int x = v;
    #pragma unroll
    for (int off = 1; off < 32; off <<= 1) {
        int y = __shfl_up_sync(0xFFFFFFFFu, x, off);
        if (lane >= off) x += y;
    }
    if (lane == 31) wsum[wid] = x;
    __syncthreads();
    if (wid == 0) {
        int s = wsum[lane];
        #pragma unroll
        for (int off = 1; off < 32; off <<= 1) {
            int y = __shfl_up_sync(0xFFFFFFFFu, s, off);
            if (lane >= off) s += y;
        }
        wsum[lane] = s;
    }
    __syncthreads();
    return x + (wid > 0 ? wsum[wid - 1] : 0);
}

// phase 1 (+ fused dinv)
__global__ __launch_bounds__(SCAN_BLK) void scan1_kernel(int n) {
    __shared__ int wsum[32];
    int idx = blockIdx.x * SCAN_BLK + threadIdx.x;
    int v = (idx < n) ? g_count[idx] : 0;
    if (idx < n) g_dinv[idx] = rsqrtf((float)v + 1.0f);   // +1 self loop
    int incl = block_scan_incl(v, wsum);
    if (idx < n) g_rowptr[idx] = incl - v;
    if (threadIdx.x == SCAN_BLK - 1) g_blocksum[blockIdx.x] = incl;
}

__global__ __launch_bounds__(SCAN_BLK) void scan2_kernel(int nb) {
    __shared__ int wsum[32];
    int t = threadIdx.x;
    int v = (t < nb) ? g_blocksum[t] : 0;
    int incl = block_scan_incl(v, wsum);
    if (t < nb) g_blockoff[t] = incl - v;
    if (t == nb - 1) g_blockoff[nb] = incl;
}

__global__ __launch_bounds__(SCAN_BLK) void scan3_kernel(int n, int nb) {
    int idx = blockIdx.x * SCAN_BLK + threadIdx.x;
    if (idx < n) {
        int r = g_rowptr[idx] + g_blockoff[blockIdx.x];
        g_rowptr[idx] = r;
        g_cursor[idx] = r;
    }
    if (idx == 0) g_rowptr[n] = g_blockoff[nb];
}

// fill CSC src list only (weights deferred to aggregation)
__global__ void fill_kernel(const int* __restrict__ ei, int E, int n) {
    int t = blockIdx.x * blockDim.x + threadIdx.x;
    int e = t * 4;
    if (e + 3 < E) {
        int4 s4 = *(const int4*)(ei + e);
        int4 d4 = *(const int4*)(ei + (size_t)E + e);
        #pragma unroll
        for (int j = 0; j < 4; j++) {
            int s = (&s4.x)[j], d = (&d4.x)[j];
            if ((unsigned)s < (unsigned)n && (unsigned)d < (unsigned)n) {
                int p = atomicAdd(&g_cursor[d], 1);
                g_csrc[p] = s;
            }
        }
    } else {
        for (; e < E; e++) {
            int s = ei[e], d = ei[(size_t)E + e];
            if ((unsigned)s < (unsigned)n && (unsigned)d < (unsigned)n) {
                int p = atomicAdd(&g_cursor[d], 1);
                g_csrc[p] = s;
            }
        }
    }
}

// ---------------- mma.sync helpers ----------------
__device__ __forceinline__ void ldsm_x4(uint32_t addr, uint32_t& r0, uint32_t& r1, uint32_t& r2, uint32_t& r3) {
    asm volatile("ldmatrix.sync.aligned.m8n8.x4.shared.b16 {%0,%1,%2,%3}, [%4];"
        : "=r"(r0), "=r"(r1), "=r"(r2), "=r"(r3) : "r"(addr));
}
__device__ __forceinline__ void mma_bf16(float* c, uint32_t a0, uint32_t a1, uint32_t a2, uint32_t a3,
                                         uint32_t b0, uint32_t b1) {
    asm volatile("mma.sync.aligned.m16n8k16.row.col.f32.bf16.bf16.f32 "
        "{%0,%1,%2,%3}, {%4,%5,%6,%7}, {%8,%9}, {%0,%1,%2,%3};"
        : "+f"(c[0]), "+f"(c[1]), "+f"(c[2]), "+f"(c[3])
        : "r"(a0), "r"(a1), "r"(a2), "r"(a3), "r"(b0), "r"(b1));
}

__device__ __forceinline__ float4 load4(const float* p) { return *(const float4*)p; }
__device__ __forceinline__ float4 half4_to_float4(uint2 raw) {
    __half2 p0 = *reinterpret_cast<__half2*>(&raw.x);
    __half2 p1 = *reinterpret_cast<__half2*>(&raw.y);
    float2 f0 = __half22float2(p0), f1 = __half22float2(p1);
    return make_float4(f0.x, f0.y, f1.x, f1.y);
}
__device__ __forceinline__ float4 load4(const __half* p) { return half4_to_float4(*(const uint2*)p); }

// ---------------- GEMM via mma.sync -> fp16 out (3-term bf16 split, fp32 accum) ----------
#define GSM_BYTES (4 * 128 * GPITCH * 2)

template <typename TIN>
__global__ __launch_bounds__(256) void gemm_mma_kernel(
    const TIN* __restrict__ A,
    const __nv_bfloat16* __restrict__ Wthi,
    const __nv_bfloat16* __restrict__ Wtlo,
    __half* __restrict__ C, int n)
{
    extern __shared__ __align__(16) __nv_bfloat16 sm[];
    __nv_bfloat16* Xhi = sm;
    __nv_bfloat16* Xlo = Xhi + 128 * GPITCH;
    __nv_bfloat16* Whi = Xlo + 128 * GPITCH;
    __nv_bfloat16* Wlo = Whi + 128 * GPITCH;

    int tid = threadIdx.x;
    int w = tid >> 5, l = tid & 31;
    int block_row = blockIdx.x * 128;

    #pragma unroll
    for (int it = 0; it < 16; it++) {
        int idx = tid + it * 256;
        int r = idx >> 5;
        int c = (idx & 31) * 4;
        int grow = block_row + r;
        float4 v = make_float4(0.f, 0.f, 0.f, 0.f);
        if (grow < n) v = load4(A + (size_t)grow * 128 + c);
        __nv_bfloat16 h0 = __float2bfloat16(v.x), h1 = __float2bfloat16(v.y);
        __nv_bfloat16 h2 = __float2bfloat16(v.z), h3 = __float2bfloat16(v.w);
        *(__nv_bfloat162*)&Xhi[r * GPITCH + c]     = __nv_bfloat162(h0, h1);
        *(__nv_bfloat162*)&Xhi[r * GPITCH + c + 2] = __nv_bfloat162(h2, h3);
        *(__nv_bfloat162*)&Xlo[r * GPITCH + c] =
            __nv_bfloat162(__float2bfloat16(v.x - __bfloat162float(h0)),
                           __float2bfloat16(v.y - __bfloat162float(h1)));
        *(__nv_bfloat162*)&Xlo[r * GPITCH + c + 2] =
            __nv_bfloat162(__float2bfloat16(v.z - __bfloat162float(h2)),
                           __float2bfloat16(v.w - __bfloat162float(h3)));
    }
    #pragma unroll
    for (int it = 0; it < 32; it++) {
        int idx = tid + it * 256;
        int r = idx >> 6;
        int c = (idx & 63) * 2;
        *(uint32_t*)&Whi[r * GPITCH + c] = *(const uint32_t*)(Wthi + (size_t)r * 128 + c);
        *(uint32_t*)&Wlo[r * GPITCH + c] = *(const uint32_t*)(Wtlo + (size_t)r * 128 + c);
    }
    __syncthreads();

    uint32_t sbase = smem_u32(sm);
    uint32_t a_off = (uint32_t)(((w * 16 + (l & 15)) * GPITCH + (l >> 4) * 8) * 2);
    uint32_t ahi_addr = sbase + a_off;
    uint32_t alo_addr = sbase + (uint32_t)(128 * GPITCH * 2) + a_off;
    uint32_t b_off = (uint32_t)((((l & 7) + ((l >> 4) << 3)) * GPITCH + ((l >> 3) & 1) * 8) * 2);
    uint32_t bhi_addr = sbase + (uint32_t)(2 * 128 * GPITCH * 2) + b_off;
    uint32_t blo_addr = sbase + (uint32_t)(3 * 128 * GPITCH * 2) + b_off;

    float acc[16][4];
    #pragma unroll
    for (int j = 0; j < 16; j++)
        #pragma unroll
        for (int q = 0; q < 4; q++) acc[j][q] = 0.0f;

    #pragma unroll
    for (int kk = 0; kk < 8; kk++) {
        uint32_t ka = kk * 32;
        uint32_t ah0, ah1, ah2, ah3, al0, al1, al2, al3;
        ldsm_x4(ahi_addr + ka, ah0, ah1, ah2, ah3);
        ldsm_x4(alo_addr + ka, al0, al1, al2, al3);
        #pragma unroll
        for (int j2 = 0; j2 < 8; j2++) {
            uint32_t boff = (uint32_t)(j2 * 16 * GPITCH * 2) + ka;
            uint32_t bh0, bh1, bh2, bh3, bl0, bl1, bl2, bl3;
            ldsm_x4(bhi_addr + boff, bh0, bh1, bh2, bh3);
            ldsm_x4(blo_addr + boff, bl0, bl1, bl2, bl3);
            mma_bf16(acc[2 * j2],     ah0, ah1, ah2, ah3, bh0, bh1);
            mma_bf16(acc[2 * j2],     al0, al1, al2, al3, bh0, bh1);
            mma_bf16(acc[2 * j2],     ah0, ah1, ah2, ah3, bl0, bl1);
            mma_bf16(acc[2 * j2 + 1], ah0, ah1, ah2, ah3, bh2, bh3);
            mma_bf16(acc[2 * j2 + 1], al0, al1, al2, al3, bh2, bh3);
            mma_bf16(acc[2 * j2 + 1], ah0, ah1, ah2, ah3, bl2, bl3);
        }
    }

    int g = l >> 2, t = l & 3;
    int row0 = block_row + w * 16 + g;
    int row1 = row0 + 8;
    #pragma unroll
    for (int j = 0; j < 16; j++) {
        int col = j * 8 + t * 2;
        if (row0 < n) *(__half2*)(C + (size_t)row0 * 128 + col) = __floats2half2_rn(acc[j][0], acc[j][1]);
        if (row1 < n) *(__half2*)(C + (size_t)row1 * 128 + col) = __floats2half2_rn(acc[j][2], acc[j][3]);
    }
}

// ---------------- aggregation: w_e = dinv[src]*dinv[i] computed on the fly ----------------
__global__ __launch_bounds__(256) void aggregate_kernel(
    const __half* __restrict__ h, const float* __restrict__ bias,
    __half* __restrict__ out, int n)
{
    int warp = (blockIdx.x * blockDim.x + threadIdx.x) >> 5;
    int lane = threadIdx.x & 31;
    if (warp >= n) return;
    int i = warp;

    float di = g_dinv[i];
    float w0 = di * di;
    float4 v = half4_to_float4(((const uint2*)(h + (size_t)i * 128))[lane]);
    float4 acc  = make_float4(v.x * w0, v.y * w0, v.z * w0, v.w * w0);
    float4 acc2 = make_float4(0.f, 0.f, 0.f, 0.f);

    int e0 = g_rowptr[i], e1 = g_rowptr[i + 1];
    int e = e0;
    for (; e + 3 < e1; e += 4) {
        int s0 = g_csrc[e];
        int s1 = g_csrc[e + 1];
        int s2 = g_csrc[e + 2];
        int s3 = g_csrc[e + 3];
        float w_0 = g_dinv[s0] * di;
        float w_1 = g_dinv[s1] * di;
        float w_2 = g_dinv[s2] * di;
        float w_3 = g_dinv[s3] * di;
        uint2 r0 = ((const uint2*)(h + (size_t)s0 * 128))[lane];
        uint2 r1 = ((const uint2*)(h + (size_t)s1 * 128))[lane];
        uint2 r2 = ((const uint2*)(h + (size_t)s2 * 128))[lane];
        uint2 r3 = ((const uint2*)(h + (size_t)s3 * 128))[lane];
        float4 h0 = half4_to_float4(r0), h1 = half4_to_float4(r1);
        float4 h2 = half4_to_float4(r2), h3 = half4_to_float4(r3);
        acc.x  = fmaf(h0.x, w_0, acc.x);  acc.y  = fmaf(h0.y, w_0, acc.y);
        acc.z  = fmaf(h0.z, w_0, acc.z);  acc.w  = fmaf(h0.w, w_0, acc.w);
        acc2.x = fmaf(h1.x, w_1, acc2.x); acc2.y = fmaf(h1.y, w_1, acc2.y);
        acc2.z = fmaf(h1.z, w_1, acc2.z); acc2.w = fmaf(h1.w, w_1, acc2.w);
        acc.x  = fmaf(h2.x, w_2, acc.x);  acc.y  = fmaf(h2.y, w_2, acc.y);
        acc.z  = fmaf(h2.z, w_2, acc.z);  acc.w  = fmaf(h2.w, w_2, acc.w);
        acc2.x = fmaf(h3.x, w_3, acc2.x); acc2.y = fmaf(h3.y, w_3, acc2.y);
        acc2.z = fmaf(h3.z, w_3, acc2.z); acc2.w = fmaf(h3.w, w_3, acc2.w);
    }
    for (; e < e1; e++) {
        int s0 = g_csrc[e];
        float w_0 = g_dinv[s0] * di;
        float4 h0 = half4_to_float4(((const uint2*)(h + (size_t)s0 * 128))[lane]);
        acc.x = fmaf(h0.x, w_0, acc.x); acc.y = fmaf(h0.y, w_0, acc.y);
        acc.z = fmaf(h0.z, w_0, acc.z); acc.w = fmaf(h0.w, w_0, acc.w);
    }
    acc.x += acc2.x; acc.y += acc2.y; acc.z += acc2.z; acc.w += acc2.w;

    float4 bb = ((const float4*)bias)[lane];
    acc.x = fmaxf(acc.x + bb.x, 0.0f);
    acc.y = fmaxf(acc.y + bb.y, 0.0f);
    acc.z = fmaxf(acc.z + bb.z, 0.0f);
    acc.w = fmaxf(acc.w + bb.w, 0.0f);
    uint2 packed;
    *reinterpret_cast<__half2*>(&packed.x) = __floats2half2_rn(acc.x, acc.y);
    *reinterpret_cast<__half2*>(&packed.y) = __floats2half2_rn(acc.z, acc.w);
    ((uint2*)(out + (size_t)i * 128))[lane] = packed;
}

// ---------------- decode ----------------
__global__ __launch_bounds__(256) void decode_kernel(
    const __half* __restrict__ z, const int* __restrict__ eli,
    float* __restrict__ out, int el)
{
    int warp = (blockIdx.x * blockDim.x + threadIdx.x) >> 5;
    int lane = threadIdx.x & 31;
    if (warp >= el) return;
    int s = eli[warp];
    int d = eli[(size_t)el + warp];
    float4 a = half4_to_float4(((const uint2*)(z + (size_t)s * 128))[lane]);
    float4 b = half4_to_float4(((const uint2*)(z + (size_t)d * 128))[lane]);
    float p = a.x * b.x + a.y * b.y + a.z * b.z + a.w * b.w;
    #pragma unroll
    for (int off = 16; off; off >>= 1) p += __shfl_down_sync(0xFFFFFFFFu, p, off);
    if (lane == 0) out[warp] = p;
}

// ---------------- launch ----------------
extern "C" void kernel_launch(void* const* d_in, const int* in_sizes, int n_in,
                              void* d_out, int out_size)
{
    const float* x   = (const float*)d_in[0];
    const int*   ei  = (const int*)d_in[1];    // int64 tensors arrive as int32
    const int*   eli = (const int*)d_in[2];
    const float* W1  = (const float*)d_in[3];
    const float* b1  = (const float*)d_in[4];
    const float* W2  = (const float*)d_in[5];
    const float* b2  = (const float*)d_in[6];
    float* out = (float*)d_out;

    int n  = in_sizes[0] / DD;
    int E  = in_sizes[1] / 2;
    int el = in_sizes[2] / 2;

    __half* h = nullptr; __half* z = nullptr;
    __nv_bfloat16 *w1hi = nullptr, *w1lo = nullptr, *w2hi = nullptr, *w2lo = nullptr;
    cudaGetSymbolAddress((void**)&h, g_h);
    cudaGetSymbolAddress((void**)&z, g_z);
    cudaGetSymbolAddress((void**)&w1hi, g_w1hi);
    cudaGetSymbolAddress((void**)&w1lo, g_w1lo);
    cudaGetSymbolAddress((void**)&w2hi, g_w2hi);
    cudaGetSymbolAddress((void**)&w2lo, g_w2lo);

    cudaFuncSetAttribute(gemm_mma_kernel<float>,  cudaFuncAttributeMaxDynamicSharedMemorySize, GSM_BYTES);
    cudaFuncSetAttribute(gemm_mma_kernel<__half>, cudaFuncAttributeMaxDynamicSharedMemorySize, GSM_BYTES);

    const int T = 256;
    int nb_n = (n + T - 1) / T;
    int nE4 = (E + 3) / 4;
    int nb_e4 = (nE4 + T - 1) / T;
    int nb_warpN = (n * 32 + T - 1) / T;
    int nb_warpL = (el * 32 + T - 1) / T;
    int nb_gemm = (n + 127) / 128;
    int nb_scan = (n + SCAN_BLK - 1) / SCAN_BLK;

    // fork a side stream: convert_w + gemm1 run concurrently with the prep chain
    cudaStream_t s2;
    cudaEvent_t evFork, evJoin;
    cudaStreamCreateWithFlags(&s2, cudaStreamNonBlocking);
    cudaEventCreateWithFlags(&evFork, cudaEventDisableTiming);
    cudaEventCreateWithFlags(&evJoin, cudaEventDisableTiming);

    cudaEventRecord(evFork, 0);
    cudaStreamWaitEvent(s2, evFork, 0);

    // side stream: weight split + layer-1 GEMM
    convert_w_kernel<<<(DD * DD + T - 1) / T, T, 0, s2>>>(W1, W2);
    gemm_mma_kernel<float><<<nb_gemm, T, GSM_BYTES, s2>>>(x, w1hi, w1lo, h, n);
    cudaEventRecord(evJoin, s2);

    // default stream: graph preprocessing
    zero_count_kernel<<<nb_n, T>>>(n);
    count_kernel<<<nb_e4, T>>>(ei, E, n);
    scan1_kernel<<<nb_scan, SCAN_BLK>>>(n);
    scan2_kernel<<<1, SCAN_BLK>>>(nb_scan);
    scan3_kernel<<<nb_scan, SCAN_BLK>>>(n, nb_scan);
    fill_kernel<<<nb_e4, T>>>(ei, E, n);

    // join: aggregation needs both fill (CSC) and gemm1 (h)
    cudaStreamWaitEvent(0, evJoin, 0);
    aggregate_kernel<<<nb_warpN, T>>>(h, b1, z, n);

    // layer 2
    gemm_mma_kernel<__half><<<nb_gemm, T, GSM_BYTES>>>(z, w2hi, w2lo, h, n);
    aggregate_kernel<<<nb_warpN, T>>>(h, b2, z, n);

    // decode
    decode_kernel<<<nb_warpL, T>>>(z, eli, out, el);
}

// round 12
// speedup vs baseline: 1.4875x; 1.0039x over previous
#include <cuda_runtime.h>
#include <cuda_bf16.h>
#include <cuda_fp16.h>
#include <cstdint>

#define NN 100000
#define EE 1600000
#define DD 128
#define SCAN_BLK 1024
#define GPITCH 136   // bf16 elements per smem row (128 + 8 pad -> conflict-free ldmatrix)

// ---------------- scratch (static device arrays; no allocation) ----------------
__device__ __half g_h[(size_t)NN * DD];   // GEMM output (fp16), aggregation input
__device__ __half g_z[(size_t)NN * DD];   // aggregation output (fp16)
__device__ int   g_count[NN];
__device__ int   g_rowptr[NN + 1];
__device__ int   g_cursor[NN];
__device__ float g_dinv[NN];
__device__ int   g_csrc[EE];
__device__ volatile int g_sagg[128];      // lookback block aggregates
__device__ volatile int g_sflag[128];     // 0 = not ready, 1 = aggregate published
// bf16 split of W1^T / W2^T : [n][k] layout (row = output col, k contiguous)
__device__ __nv_bfloat16 g_w1hi[DD * DD];
__device__ __nv_bfloat16 g_w1lo[DD * DD];
__device__ __nv_bfloat16 g_w2hi[DD * DD];
__device__ __nv_bfloat16 g_w2lo[DD * DD];

__device__ __forceinline__ uint32_t smem_u32(const void* p) {
    uint32_t a;
    asm("{ .reg .u64 t; cvta.to.shared.u64 t, %1; cvt.u32.u64 %0, t; }" : "=r"(a) : "l"(p));
    return a;
}

// ---------------- preprocessing kernels ----------------
__global__ void zero_count_kernel(int n) {
    int i = blockIdx.x * blockDim.x + threadIdx.x;
    if (i < n) g_count[i] = 0;
    if (i < 128) { g_sflag[i] = 0; g_sagg[i] = 0; }
}

// split W1/W2 to bf16 hi/lo (side stream)
__global__ void convert_w_kernel(const float* __restrict__ W1, const float* __restrict__ W2) {
    int i = blockIdx.x * blockDim.x + threadIdx.x;
    if (i >= DD * DD) return;
    int nn = i >> 7, kk = i & 127;
    float w1 = W1[kk * DD + nn];
    __nv_bfloat16 h1 = __float2bfloat16(w1);
    g_w1hi[nn * DD + kk] = h1;
    g_w1lo[nn * DD + kk] = __float2bfloat16(w1 - __bfloat162float(h1));
    float w2 = W2[kk * DD + nn];
    __nv_bfloat16 h2 = __float2bfloat16(w2);
    g_w2hi[nn * DD + kk] = h2;
    g_w2lo[nn * DD + kk] = __float2bfloat16(w2 - __bfloat162float(h2));
}

// 4 edges per thread (int4 load of dst)
__global__ void count_kernel(const int* __restrict__ ei, int E, int n) {
    int t = blockIdx.x * blockDim.x + threadIdx.x;
    int e = t * 4;
    if (e + 3 < E) {
        int4 d4 = *(const int4*)(ei + (size_t)E + e);
        if ((unsigned)d4.x < (unsigned)n) atomicAdd(&g_count[d4.x], 1);
        if ((unsigned)d4.y < (unsigned)n) atomicAdd(&g_count[d4.y], 1);
        if ((unsigned)d4.z < (unsigned)n) atomicAdd(&g_count[d4.z], 1);
        if ((unsigned)d4.w < (unsigned)n) atomicAdd(&g_count[d4.w], 1);
    } else {
        for (; e < E; e++) {
            int d = ei[(size_t)E + e];
            if ((unsigned)d < (unsigned)n) atomicAdd(&g_count[d], 1);
        }
    }
}

__device__ __forceinline__ int block_scan_incl(int v, int* wsum) {
    int lane = threadIdx.x & 31, wid = threadIdx.x >> 5;
    int x = v;
    #pragma unroll
    for (int off = 1; off < 32; off <<= 1) {
        int y = __shfl_up_sync(0xFFFFFFFFu, x, off);
        if (lane >= off) x += y;
    }
    if (lane == 31) wsum[wid] = x;
    __syncthreads();
    if (wid == 0) {
        int s = wsum[lane];
        #pragma unroll
        for (int off = 1; off < 32; off <<= 1) {
            int y = __shfl_up_sync(0xFFFFFFFFu, s, off);
            if (lane >= off) s += y;
        }
        wsum[lane] = s;
    }
    __syncthreads();
    return x + (wid > 0 ? wsum[wid - 1] : 0);
}

// single-pass scan with aggregate-publishing lookback (+ fused dinv/cursor)
// all nb (<=98) blocks are co-resident on 148 SMs, so spinning on predecessors is safe
__global__ __launch_bounds__(SCAN_BLK) void scan_kernel(int n, int nb) {
    __shared__ int wsum[32];
    __shared__ int s_prefix;
    int bid = blockIdx.x;
    int idx = bid * SCAN_BLK + threadIdx.x;
    int v = (idx < n) ? g_count[idx] : 0;
    if (idx < n) g_dinv[idx] = rsqrtf((float)v + 1.0f);   // +1 self loop
    int incl = block_scan_incl(v, wsum);

    // publish this block's aggregate
    if (threadIdx.x == SCAN_BLK - 1) {
        g_sagg[bid] = incl;
        __threadfence();
        g_sflag[bid] = 1;
    }
    // warp 0: sum all predecessor aggregates (warp-parallel, no serial chain)
    if (threadIdx.x < 32) {
        int sum = 0;
        for (int j = (int)threadIdx.x; j < bid; j += 32) {
            while (g_sflag[j] == 0) { }
            sum += g_sagg[j];
        }
        #pragma unroll
        for (int o = 16; o; o >>= 1) sum += __shfl_down_sync(0xFFFFFFFFu, sum, o);
        if (threadIdx.x == 0) s_prefix = sum;
    }
    __syncthreads();

    int r = s_prefix + incl - v;
    if (idx < n) { g_rowptr[idx] = r; g_cursor[idx] = r; }
    if (bid == nb - 1 && threadIdx.x == SCAN_BLK - 1)
        g_rowptr[n] = s_prefix + incl;
}

// fill CSC src list only (weights deferred to aggregation)
__global__ void fill_kernel(const int* __restrict__ ei, int E, int n) {
    int t = blockIdx.x * blockDim.x + threadIdx.x;
    int e = t * 4;
    if (e + 3 < E) {
        int4 s4 = *(const int4*)(ei + e);
        int4 d4 = *(const int4*)(ei + (size_t)E + e);
        #pragma unroll
        for (int j = 0; j < 4; j++) {
            int s = (&s4.x)[j], d = (&d4.x)[j];
            if ((unsigned)s < (unsigned)n && (unsigned)d < (unsigned)n) {
                int p = atomicAdd(&g_cursor[d], 1);
                g_csrc[p] = s;
            }
        }
    } else {
        for (; e < E; e++) {
            int s = ei[e], d = ei[(size_t)E + e];
            if ((unsigned)s < (unsigned)n && (unsigned)d < (unsigned)n) {
                int p = atomicAdd(&g_cursor[d], 1);
                g_csrc[p] = s;
            }
        }
    }
}

// ---------------- mma.sync helpers ----------------
__device__ __forceinline__ void ldsm_x4(uint32_t addr, uint32_t& r0, uint32_t& r1, uint32_t& r2, uint32_t& r3) {
    asm volatile("ldmatrix.sync.aligned.m8n8.x4.shared.b16 {%0,%1,%2,%3}, [%4];"
        : "=r"(r0), "=r"(r1), "=r"(r2), "=r"(r3) : "r"(addr));
}
__device__ __forceinline__ void mma_bf16(float* c, uint32_t a0, uint32_t a1, uint32_t a2, uint32_t a3,
                                         uint32_t b0, uint32_t b1) {
    asm volatile("mma.sync.aligned.m16n8k16.row.col.f32.bf16.bf16.f32 "
        "{%0,%1,%2,%3}, {%4,%5,%6,%7}, {%8,%9}, {%0,%1,%2,%3};"
        : "+f"(c[0]), "+f"(c[1]), "+f"(c[2]), "+f"(c[3])
        : "r"(a0), "r"(a1), "r"(a2), "r"(a3), "r"(b0), "r"(b1));
}

__device__ __forceinline__ float4 load4(const float* p) { return *(const float4*)p; }
__device__ __forceinline__ float4 half4_to_float4(uint2 raw) {
    __half2 p0 = *reinterpret_cast<__half2*>(&raw.x);
    __half2 p1 = *reinterpret_cast<__half2*>(&raw.y);
    float2 f0 = __half22float2(p0), f1 = __half22float2(p1);
    return make_float4(f0.x, f0.y, f1.x, f1.y);
}
__device__ __forceinline__ float4 load4(const __half* p) { return half4_to_float4(*(const uint2*)p); }

// ---------------- GEMM via mma.sync -> fp16 out (3-term bf16 split, fp32 accum) ----------
#define GSM_BYTES (4 * 128 * GPITCH * 2)

template <typename TIN>
__global__ __launch_bounds__(256) void gemm_mma_kernel(
    const TIN* __restrict__ A,
    const __nv_bfloat16* __restrict__ Wthi,
    const __nv_bfloat16* __restrict__ Wtlo,
    __half* __restrict__ C, int n)
{
    extern __shared__ __align__(16) __nv_bfloat16 sm[];
    __nv_bfloat16* Xhi = sm;
    __nv_bfloat16* Xlo = Xhi + 128 * GPITCH;
    __nv_bfloat16* Whi = Xlo + 128 * GPITCH;
    __nv_bfloat16* Wlo = Whi + 128 * GPITCH;

    int tid = threadIdx.x;
    int w = tid >> 5, l = tid & 31;
    int block_row = blockIdx.x * 128;

    #pragma unroll
    for (int it = 0; it < 16; it++) {
        int idx = tid + it * 256;
        int r = idx >> 5;
        int c = (idx & 31) * 4;
        int grow = block_row + r;
        float4 v = make_float4(0.f, 0.f, 0.f, 0.f);
        if (grow < n) v = load4(A + (size_t)grow * 128 + c);
        __nv_bfloat16 h0 = __float2bfloat16(v.x), h1 = __float2bfloat16(v.y);
        __nv_bfloat16 h2 = __float2bfloat16(v.z), h3 = __float2bfloat16(v.w);
        *(__nv_bfloat162*)&Xhi[r * GPITCH + c]     = __nv_bfloat162(h0, h1);
        *(__nv_bfloat162*)&Xhi[r * GPITCH + c + 2] = __nv_bfloat162(h2, h3);
        *(__nv_bfloat162*)&Xlo[r * GPITCH + c] =
            __nv_bfloat162(__float2bfloat16(v.x - __bfloat162float(h0)),
                           __float2bfloat16(v.y - __bfloat162float(h1)));
        *(__nv_bfloat162*)&Xlo[r * GPITCH + c + 2] =
            __nv_bfloat162(__float2bfloat16(v.z - __bfloat162float(h2)),
                           __float2bfloat16(v.w - __bfloat162float(h3)));
    }
    #pragma unroll
    for (int it = 0; it < 32; it++) {
        int idx = tid + it * 256;
        int r = idx >> 6;
        int c = (idx & 63) * 2;
        *(uint32_t*)&Whi[r * GPITCH + c] = *(const uint32_t*)(Wthi + (size_t)r * 128 + c);
        *(uint32_t*)&Wlo[r * GPITCH + c] = *(const uint32_t*)(Wtlo + (size_t)r * 128 + c);
    }
    __syncthreads();

    uint32_t sbase = smem_u32(sm);
    uint32_t a_off = (uint32_t)(((w * 16 + (l & 15)) * GPITCH + (l >> 4) * 8) * 2);
    uint32_t ahi_addr = sbase + a_off;
    uint32_t alo_addr = sbase + (uint32_t)(128 * GPITCH * 2) + a_off;
    uint32_t b_off = (uint32_t)((((l & 7) + ((l >> 4) << 3)) * GPITCH + ((l >> 3) & 1) * 8) * 2);
    uint32_t bhi_addr = sbase + (uint32_t)(2 * 128 * GPITCH * 2) + b_off;
    uint32_t blo_addr = sbase + (uint32_t)(3 * 128 * GPITCH * 2) + b_off;

    float acc[16][4];
    #pragma unroll
    for (int j = 0; j < 16; j++)
        #pragma unroll
        for (int q = 0; q < 4; q++) acc[j][q] = 0.0f;

    #pragma unroll
    for (int kk = 0; kk < 8; kk++) {
        uint32_t ka = kk * 32;
        uint32_t ah0, ah1, ah2, ah3, al0, al1, al2, al3;
        ldsm_x4(ahi_addr + ka, ah0, ah1, ah2, ah3);
        ldsm_x4(alo_addr + ka, al0, al1, al2, al3);
        #pragma unroll
        for (int j2 = 0; j2 < 8; j2++) {
            uint32_t boff = (uint32_t)(j2 * 16 * GPITCH * 2) + ka;
            uint32_t bh0, bh1, bh2, bh3, bl0, bl1, bl2, bl3;
            ldsm_x4(bhi_addr + boff, bh0, bh1, bh2, bh3);
            ldsm_x4(blo_addr + boff, bl0, bl1, bl2, bl3);
            mma_bf16(acc[2 * j2],     ah0, ah1, ah2, ah3, bh0, bh1);
            mma_bf16(acc[2 * j2],     al0, al1, al2, al3, bh0, bh1);
            mma_bf16(acc[2 * j2],     ah0, ah1, ah2, ah3, bl0, bl1);
            mma_bf16(acc[2 * j2 + 1], ah0, ah1, ah2, ah3, bh2, bh3);
            mma_bf16(acc[2 * j2 + 1], al0, al1, al2, al3, bh2, bh3);
            mma_bf16(acc[2 * j2 + 1], ah0, ah1, ah2, ah3, bl2, bl3);
        }
    }

    int g = l >> 2, t = l & 3;
    int row0 = block_row + w * 16 + g;
    int row1 = row0 + 8;
    #pragma unroll
    for (int j = 0; j < 16; j++) {
        int col = j * 8 + t * 2;
        if (row0 < n) *(__half2*)(C + (size_t)row0 * 128 + col) = __floats2half2_rn(acc[j][0], acc[j][1]);
        if (row1 < n) *(__half2*)(C + (size_t)row1 * 128 + col) = __floats2half2_rn(acc[j][2], acc[j][3]);
    }
}

// ---------------- aggregation: w_e = dinv[src]*dinv[i] computed on the fly ----------------
__global__ __launch_bounds__(256) void aggregate_kernel(
    const __half* __restrict__ h, const float* __restrict__ bias,
    __half* __restrict__ out, int n)
{
    int warp = (blockIdx.x * blockDim.x + threadIdx.x) >> 5;
    int lane = threadIdx.x & 31;
    if (warp >= n) return;
    int i = warp;

    float di = g_dinv[i];
    float w0 = di * di;
    float4 v = half4_to_float4(((const uint2*)(h + (size_t)i * 128))[lane]);
    float4 acc  = make_float4(v.x * w0, v.y * w0, v.z * w0, v.w * w0);
    float4 acc2 = make_float4(0.f, 0.f, 0.f, 0.f);

    int e0 = g_rowptr[i], e1 = g_rowptr[i + 1];
    int e = e0;
    for (; e + 3 < e1; e += 4) {
        int s0 = g_csrc[e];
        int s1 = g_csrc[e + 1];
        int s2 = g_csrc[e + 2];
        int s3 = g_csrc[e + 3];
        float w_0 = g_dinv[s0] * di;
        float w_1 = g_dinv[s1] * di;
        float w_2 = g_dinv[s2] * di;
        float w_3 = g_dinv[s3] * di;
        uint2 r0 = ((const uint2*)(h + (size_t)s0 * 128))[lane];
        uint2 r1 = ((const uint2*)(h + (size_t)s1 * 128))[lane];
        uint2 r2 = ((const uint2*)(h + (size_t)s2 * 128))[lane];
        uint2 r3 = ((const uint2*)(h + (size_t)s3 * 128))[lane];
        float4 h0 = half4_to_float4(r0), h1 = half4_to_float4(r1);
        float4 h2 = half4_to_float4(r2), h3 = half4_to_float4(r3);
        acc.x  = fmaf(h0.x, w_0, acc.x);  acc.y  = fmaf(h0.y, w_0, acc.y);
        acc.z  = fmaf(h0.z, w_0, acc.z);  acc.w  = fmaf(h0.w, w_0, acc.w);
        acc2.x = fmaf(h1.x, w_1, acc2.x); acc2.y = fmaf(h1.y, w_1, acc2.y);
        acc2.z = fmaf(h1.z, w_1, acc2.z); acc2.w = fmaf(h1.w, w_1, acc2.w);
        acc.x  = fmaf(h2.x, w_2, acc.x);  acc.y  = fmaf(h2.y, w_2, acc.y);
        acc.z  = fmaf(h2.z, w_2, acc.z);  acc.w  = fmaf(h2.w, w_2, acc.w);
        acc2.x = fmaf(h3.x, w_3, acc2.x); acc2.y = fmaf(h3.y, w_3, acc2.y);
        acc2.z = fmaf(h3.z, w_3, acc2.z); acc2.w = fmaf(h3.w, w_3, acc2.w);
    }
    for (; e < e1; e++) {
        int s0 = g_csrc[e];
        float w_0 = g_dinv[s0] * di;
        float4 h0 = half4_to_float4(((const uint2*)(h + (size_t)s0 * 128))[lane]);
        acc.x = fmaf(h0.x, w_0, acc.x); acc.y = fmaf(h0.y, w_0, acc.y);
        acc.z = fmaf(h0.z, w_0, acc.z); acc.w = fmaf(h0.w, w_0, acc.w);
    }
    acc.x += acc2.x; acc.y += acc2.y; acc.z += acc2.z; acc.w += acc2.w;

    float4 bb = ((const float4*)bias)[lane];
    acc.x = fmaxf(acc.x + bb.x, 0.0f);
    acc.y = fmaxf(acc.y + bb.y, 0.0f);
    acc.z = fmaxf(acc.z + bb.z, 0.0f);
    acc.w = fmaxf(acc.w + bb.w, 0.0f);
    uint2 packed;
    *reinterpret_cast<__half2*>(&packed.x) = __floats2half2_rn(acc.x, acc.y);
    *reinterpret_cast<__half2*>(&packed.y) = __floats2half2_rn(acc.z, acc.w);
    ((uint2*)(out + (size_t)i * 128))[lane] = packed;
}

// ---------------- decode ----------------
__global__ __launch_bounds__(256) void decode_kernel(
    const __half* __restrict__ z, const int* __restrict__ eli,
    float* __restrict__ out, int el)
{
    int warp = (blockIdx.x * blockDim.x + threadIdx.x) >> 5;
    int lane = threadIdx.x & 31;
    if (warp >= el) return;
    int s = eli[warp];
    int d = eli[(size_t)el + warp];
    float4 a = half4_to_float4(((const uint2*)(z + (size_t)s * 128))[lane]);
    float4 b = half4_to_float4(((const uint2*)(z + (size_t)d * 128))[lane]);
    float p = a.x * b.x + a.y * b.y + a.z * b.z + a.w * b.w;
    #pragma unroll
    for (int off = 16; off; off >>= 1) p += __shfl_down_sync(0xFFFFFFFFu, p, off);
    if (lane == 0) out[warp] = p;
}

// ---------------- launch ----------------
extern "C" void kernel_launch(void* const* d_in, const int* in_sizes, int n_in,
                              void* d_out, int out_size)
{
    const float* x   = (const float*)d_in[0];
    const int*   ei  = (const int*)d_in[1];    // int64 tensors arrive as int32
    const int*   eli = (const int*)d_in[2];
    const float* W1  = (const float*)d_in[3];
    const float* b1  = (const float*)d_in[4];
    const float* W2  = (const float*)d_in[5];
    const float* b2  = (const float*)d_in[6];
    float* out = (float*)d_out;

    int n  = in_sizes[0] / DD;
    int E  = in_sizes[1] / 2;
    int el = in_sizes[2] / 2;

    __half* h = nullptr; __half* z = nullptr;
    __nv_bfloat16 *w1hi = nullptr, *w1lo = nullptr, *w2hi = nullptr, *w2lo = nullptr;
    cudaGetSymbolAddress((void**)&h, g_h);
    cudaGetSymbolAddress((void**)&z, g_z);
    cudaGetSymbolAddress((void**)&w1hi, g_w1hi);
    cudaGetSymbolAddress((void**)&w1lo, g_w1lo);
    cudaGetSymbolAddress((void**)&w2hi, g_w2hi);
    cudaGetSymbolAddress((void**)&w2lo, g_w2lo);

    cudaFuncSetAttribute(gemm_mma_kernel<float>,  cudaFuncAttributeMaxDynamicSharedMemorySize, GSM_BYTES);
    cudaFuncSetAttribute(gemm_mma_kernel<__half>, cudaFuncAttributeMaxDynamicSharedMemorySize, GSM_BYTES);

    const int T = 256;
    int nb_n = (n + T - 1) / T;
    int nE4 = (E + 3) / 4;
    int nb_e4 = (nE4 + T - 1) / T;
    int nb_warpN = (n * 32 + T - 1) / T;
    int nb_warpL = (el * 32 + T - 1) / T;
    int nb_gemm = (n + 127) / 128;
    int nb_scan = (n + SCAN_BLK - 1) / SCAN_BLK;

    // fork a side stream: convert_w + gemm1 run concurrently with the prep chain
    cudaStream_t s2;
    cudaEvent_t evFork, evJoin;
    cudaStreamCreateWithFlags(&s2, cudaStreamNonBlocking);
    cudaEventCreateWithFlags(&evFork, cudaEventDisableTiming);
    cudaEventCreateWithFlags(&evJoin, cudaEventDisableTiming);

    cudaEventRecord(evFork, 0);
    cudaStreamWaitEvent(s2, evFork, 0);

    // side stream: weight split + layer-1 GEMM
    convert_w_kernel<<<(DD * DD + T - 1) / T, T, 0, s2>>>(W1, W2);
    gemm_mma_kernel<float><<<nb_gemm, T, GSM_BYTES, s2>>>(x, w1hi, w1lo, h, n);
    cudaEventRecord(evJoin, s2);

    // default stream: graph preprocessing
    zero_count_kernel<<<nb_n, T>>>(n);
    count_kernel<<<nb_e4, T>>>(ei, E, n);
    scan_kernel<<<nb_scan, SCAN_BLK>>>(n, nb_scan);   // single-pass lookback scan
    fill_kernel<<<nb_e4, T>>>(ei, E, n);

    // join: aggregation needs both fill (CSC) and gemm1 (h)
    cudaStreamWaitEvent(0, evJoin, 0);
    aggregate_kernel<<<nb_warpN, T>>>(h, b1, z, n);

    // layer 2
    gemm_mma_kernel<__half><<<nb_gemm, T, GSM_BYTES>>>(z, w2hi, w2lo, h, n);
    aggregate_kernel<<<nb_warpN, T>>>(h, b2, z, n);

    // decode
    decode_kernel<<<nb_warpL, T>>>(z, eli, out, el);
}